// round 1
// baseline (speedup 1.0000x reference)
#include <cuda_runtime.h>
#include <math.h>

#define KGT 50
#define NA 3
#define NC 80
#define BMAX 16
#define NMAX (BMAX*52*52*NA)

__device__ float  g_max_iou[NMAX];
__device__ int    g_win[NMAX];
__device__ float  g_delta[BMAX*KGT*4];
__device__ int    g_cls[BMAX*KGT];
__device__ float  g_obji[BMAX*KGT];
__device__ int    g_has_pos[BMAX];
__device__ int    g_num_obj[BMAX];
__device__ double g_acc;

__device__ __forceinline__ float sigf(float x){ return 1.0f/(1.0f+expf(-x)); }

__device__ __forceinline__ float iou_f(float ax,float ay,float aw,float ah,
                                       float bx,float by,float bw,float bh){
    float tlx=fmaxf(ax-aw*0.5f, bx-bw*0.5f);
    float tly=fmaxf(ay-ah*0.5f, by-bh*0.5f);
    float brx=fminf(ax+aw*0.5f, bx+bw*0.5f);
    float bry=fminf(ay+ah*0.5f, by+bh*0.5f);
    float wx=fmaxf(brx-tlx,0.0f), wy=fmaxf(bry-tly,0.0f);
    float inter=wx*wy;
    return inter/(aw*ah + bw*bh - inter);
}

__global__ void k_init(){ g_acc = 0.0; }

__global__ void k_clear(int N){
    int i=blockIdx.x*blockDim.x+threadIdx.x;
    if(i<N) g_win[i]=-1;
    if(i<BMAX) g_has_pos[i]=0;
}

// One thread per (a,hw) cell of batch b = blockIdx.y.
// idx = a*HW + hw so consecutive threads share a channel -> coalesced loads.
__global__ void k_pass1(const float* __restrict__ out, const float* __restrict__ tgt,
                        const float* __restrict__ anc, int W){
    __shared__ float s_gt[KGT][4];
    __shared__ int   s_v[KGT];
    __shared__ float s_anc[NA*2];
    int b=blockIdx.y, tid=threadIdx.x;
    int HW=W*W;
    if(tid<KGT){
        const float* t=tgt+(size_t)(b*KGT+tid)*5;
        float t0=t[0],t1=t[1],t2=t[2],t3=t[3],t4=t[4];
        s_v[tid]=((t0+t1+t2+t3+t4)>0.0f) ? 1 : 0;
        s_gt[tid][0]=t0*(float)W; s_gt[tid][1]=t1*(float)W;
        s_gt[tid][2]=t2*(float)W; s_gt[tid][3]=t3*(float)W;
    }
    if(tid<NA*2) s_anc[tid]=anc[tid];
    __syncthreads();
    int idx=blockIdx.x*blockDim.x+tid;
    if(idx>=NA*HW) return;
    int a=idx/HW, hw=idx-a*HW;
    int x=hw%W, y=hw/W;
    const float* base = out + (size_t)(b*255 + a*85)*HW + hw;
    float px=sigf(base[0])+(float)x;
    float py=sigf(base[(size_t)HW])+(float)y;
    float pw=expf(base[(size_t)2*HW])*s_anc[a*2+0];
    float ph=expf(base[(size_t)3*HW])*s_anc[a*2+1];
    float m=-1.0f;
    #pragma unroll 5
    for(int k=0;k<KGT;k++){
        if(s_v[k]){
            float v=iou_f(px,py,pw,ph,s_gt[k][0],s_gt[k][1],s_gt[k][2],s_gt[k][3]);
            m=fmaxf(m,v);
        }
    }
    int n=b*HW*NA + hw*NA + a;
    g_max_iou[n]=m;
    if(m>0.7f) atomicOr(&g_has_pos[b],1);
}

// One block per batch: GT -> cell/anchor assignment with last-valid-wins dedup
// (equivalent to segment_max over rank), writes winner records + win[] scatter.
__global__ void k_pass2(const float* __restrict__ tgt, const float* __restrict__ anc, int W){
    __shared__ int s_f[KGT];
    __shared__ int s_v[KGT];
    int b=blockIdx.x, k=threadIdx.x;
    int HW=W*W;
    int valid=0, f=0, cx=0, cy=0, astar=0, cls=0;
    float gx=0.f,gy=0.f,gw=0.f,gh=0.f;
    if(k<KGT){
        const float* t=tgt+(size_t)(b*KGT+k)*5;
        float t0=t[0],t1=t[1],t2=t[2],t3=t[3],t4=t[4];
        valid=((t0+t1+t2+t3+t4)>0.0f) ? 1 : 0;
        gx=t0*(float)W; gy=t1*(float)W; gw=t2*(float)W; gh=t3*(float)W;
        cx=min(max((int)floorf(gx),0),W-1);
        cy=min(max((int)floorf(gy),0),W-1);
        float best=-1e30f;
        for(int a=0;a<NA;a++){
            float v=iou_f((float)cx+0.5f,(float)cy+0.5f,anc[a*2],anc[a*2+1],gx,gy,gw,gh);
            if(v>best){best=v;astar=a;}   // strict > : first max, matching argmax
        }
        f=(cy*W+cx)*NA+astar;
        cls=(int)t4;
        s_f[k]=f; s_v[k]=valid;
    }
    __syncthreads();
    if(k==0){
        int c=0;
        for(int i=0;i<KGT;i++) c+=s_v[i];
        g_num_obj[b]=c;
    }
    if(k<KGT && valid){
        bool win=true;
        for(int k2=k+1;k2<KGT;k2++)
            if(s_v[k2] && s_f[k2]==f){win=false;break;}
        if(win){
            int rec=b*KGT+k;
            int n=b*HW*NA+f;
            g_win[n]=rec;
            g_delta[rec*4+0]=gx-(float)cx;
            g_delta[rec*4+1]=gy-(float)cy;
            g_delta[rec*4+2]=gw/anc[astar*2+0];
            g_delta[rec*4+3]=gh/anc[astar*2+1];
            g_cls[rec]=cls;
            g_obji[rec]=g_max_iou[n];
        }
    }
}

// Per-cell loss accumulation; block reduce in double -> atomicAdd.
__global__ void k_pass3(const float* __restrict__ out, int W){
    __shared__ double s_red[256];
    int b=blockIdx.y, tid=threadIdx.x;
    int HW=W*W;
    int idx=blockIdx.x*blockDim.x+tid;
    double v=0.0;
    if(idx<NA*HW){
        int a=idx/HW, hw=idx-a*HW;
        int n=b*HW*NA+hw*NA+a;
        const float* base = out + (size_t)(b*255+a*85)*HW + hw;
        float conf=sigf(base[(size_t)4*HW]);
        int rec=g_win[n];
        if(rec>=0){
            // objectness term: mask = OBJ_SCALE = 5
            float ti=g_obji[rec];
            float di=5.0f*(conf-ti);
            // box term
            float bx=sigf(base[0])               -g_delta[rec*4+0];
            float by=sigf(base[(size_t)HW])      -g_delta[rec*4+1];
            float bw=expf(base[(size_t)2*HW])    -g_delta[rec*4+2];
            float bh=expf(base[(size_t)3*HW])    -g_delta[rec*4+3];
            // class term: logsumexp - target logit
            float mx=-1e30f;
            for(int c=0;c<NC;c++) mx=fmaxf(mx, base[(size_t)(5+c)*HW]);
            float s=0.0f;
            for(int c=0;c<NC;c++) s+=expf(base[(size_t)(5+c)*HW]-mx);
            float lse=mx+logf(s);
            float tl=base[(size_t)(5+g_cls[rec])*HW];
            v = 0.5*(double)(di*di)
              + 0.5*(double)(bx*bx+by*by+bw*bw+bh*bh)
              + (double)(lse-tl);
        } else {
            // noobj: mask 1 unless (num_obj==0) or (has_pos && max_iou>=0.7)
            if(g_num_obj[b]>0 && !(g_has_pos[b] && (g_max_iou[n]>=0.7f)))
                v = 0.5*(double)(conf*conf);
        }
    }
    s_red[tid]=v;
    __syncthreads();
    for(int s=128;s>0;s>>=1){
        if(tid<s) s_red[tid]+=s_red[tid+s];
        __syncthreads();
    }
    if(tid==0) atomicAdd(&g_acc, s_red[0]);
}

__global__ void k_final(float* outp, int B){
    outp[0]=(float)(g_acc/((double)B*3.0));
}

extern "C" void kernel_launch(void* const* d_in, const int* in_sizes, int n_in,
                              void* d_out, int out_size){
    const float* o[3]={(const float*)d_in[0],(const float*)d_in[1],(const float*)d_in[2]};
    const float* tgt=(const float*)d_in[3];
    const float* anc=(const float*)d_in[4];
    int B = in_sizes[3]/(KGT*5);
    int Ws[3];
    for(int i=0;i<3;i++){
        int hw=in_sizes[i]/(B*255);
        int w=1; while(w*w<hw) w++;
        Ws[i]=w;
    }
    // o1 (13x13) -> anchors[6:9], o2 (26x26) -> anchors[3:6], o3 (52x52) -> anchors[0:3]
    int aoff[3]={12,6,0};

    k_init<<<1,1>>>();
    for(int s=0;s<3;s++){
        int W=Ws[s], HW=W*W;
        int cells=NA*HW;
        int N=B*cells;
        k_clear<<<(N+255)/256,256>>>(N);
        dim3 g((cells+255)/256, B);
        k_pass1<<<g,256>>>(o[s], tgt, anc+aoff[s], W);
        k_pass2<<<B,64>>>(tgt, anc+aoff[s], W);
        k_pass3<<<g,256>>>(o[s], W);
    }
    k_final<<<1,1>>>((float*)d_out, B);
}

// round 2
// speedup vs baseline: 1.8777x; 1.8777x over previous
#include <cuda_runtime.h>
#include <math.h>

#define KGT 50
#define NA 3
#define NC 80
#define GX 32            // blocks per (scale,batch) chunk axis
#define BMAX 16
#define NPART (3*BMAX*GX)

__device__ double g_pmain[NPART];
__device__ double g_phigh[NPART];
__device__ int    g_php[NPART];

__device__ __forceinline__ float sigf(float x){ return 1.0f/(1.0f+expf(-x)); }

__device__ __forceinline__ float iou_f(float ax,float ay,float aw,float ah,
                                       float bx,float by,float bw,float bh){
    float tlx=fmaxf(ax-aw*0.5f, bx-bw*0.5f);
    float tly=fmaxf(ay-ah*0.5f, by-bh*0.5f);
    float brx=fminf(ax+aw*0.5f, bx+bw*0.5f);
    float bry=fminf(ay+ah*0.5f, by+bh*0.5f);
    float wx=fmaxf(brx-tlx,0.0f), wy=fmaxf(bry-tly,0.0f);
    float inter=wx*wy;
    return inter/(aw*ah + bw*bh - inter);
}

// Fused kernel: per block = 256 cells of one (scale, batch).
// Each block recomputes GT->cell/anchor assignment + dedup in shared (cheap),
// then evaluates every loss term locally. has_pos coupling handled by emitting
// (main, high, hp) partials per block; finalize combines.
__global__ void __launch_bounds__(256) k_main(
        const float* __restrict__ o0, const float* __restrict__ o1,
        const float* __restrict__ o2, const float* __restrict__ tgt,
        const float* __restrict__ anc,
        int W0, int W1, int W2, int B){
    int s = blockIdx.z, b = blockIdx.y, bx = blockIdx.x;
    const float* out = (s==0) ? o0 : (s==1 ? o1 : o2);
    int W = (s==0) ? W0 : (s==1 ? W1 : W2);
    const float* Aptr = anc + ((s==0) ? 12 : (s==1 ? 6 : 0));
    int HW = W*W, cells = NA*HW;
    int pidx = (s*B + b)*GX + bx;
    int tid = threadIdx.x;

    if (bx*256 >= cells){                 // inactive block: deterministic zeros
        if (tid == 0){ g_pmain[pidx]=0.0; g_phigh[pidx]=0.0; g_php[pidx]=0; }
        return;
    }

    __shared__ float s_gt[KGT][4];
    __shared__ int   s_v[KGT], s_f[KGT], s_w[KGT], s_cls[KGT];
    __shared__ float s_d[KGT][4];
    __shared__ float s_anc[NA*2];
    __shared__ int   s_numobj, s_hp;
    __shared__ double s_rm[256], s_rh[256];

    // phase 1: load GTs + anchors
    if (tid == 0) s_hp = 0;
    if (tid < NA*2) s_anc[tid] = Aptr[tid];
    if (tid < KGT){
        const float* t = tgt + (size_t)(b*KGT + tid)*5;
        float t0=t[0], t1=t[1], t2=t[2], t3=t[3], t4=t[4];
        s_v[tid]   = ((t0+t1+t2+t3+t4) > 0.0f) ? 1 : 0;
        s_gt[tid][0]=t0*(float)W; s_gt[tid][1]=t1*(float)W;
        s_gt[tid][2]=t2*(float)W; s_gt[tid][3]=t3*(float)W;
        s_cls[tid] = (int)t4;
    }
    __syncthreads();

    // phase 2: per-GT cell + best anchor + delta
    if (tid < KGT){
        float gx=s_gt[tid][0], gy=s_gt[tid][1], gw=s_gt[tid][2], gh=s_gt[tid][3];
        int cx = min(max((int)floorf(gx),0), W-1);
        int cy = min(max((int)floorf(gy),0), W-1);
        int astar = 0; float best = -1e30f;
        #pragma unroll
        for (int a=0; a<NA; a++){
            float v = iou_f((float)cx+0.5f, (float)cy+0.5f, s_anc[a*2], s_anc[a*2+1],
                            gx, gy, gw, gh);
            if (v > best){ best = v; astar = a; }   // strict >: first max (argmax)
        }
        s_f[tid] = (cy*W + cx)*NA + astar;
        s_d[tid][0] = gx - (float)cx;
        s_d[tid][1] = gy - (float)cy;
        s_d[tid][2] = gw / s_anc[astar*2+0];
        s_d[tid][3] = gh / s_anc[astar*2+1];
    }
    if (tid == 0){
        int c = 0;
        for (int i=0;i<KGT;i++) c += s_v[i];
        s_numobj = c;
    }
    __syncthreads();

    // phase 3: dedup = last valid GT with a given f wins (segment_max over rank)
    if (tid < KGT){
        int win = s_v[tid];
        if (win){
            int f = s_f[tid];
            for (int k2 = tid+1; k2 < KGT; k2++)
                if (s_v[k2] && s_f[k2]==f){ win = 0; break; }
        }
        s_w[tid] = win;
    }
    __syncthreads();

    // phase 4: per-cell loss terms
    int idx = bx*256 + tid;
    double vm = 0.0, vh = 0.0;
    if (idx < cells){
        int a = idx / HW, hw = idx - a*HW;
        int x = hw % W, y = hw / W;
        const float* base = out + (size_t)(b*255 + a*85)*HW + hw;
        float px = sigf(base[0]) + (float)x;
        float py = sigf(base[(size_t)HW]) + (float)y;
        float ew = expf(base[(size_t)2*HW]);
        float eh = expf(base[(size_t)3*HW]);
        float pw = ew * s_anc[a*2+0];
        float ph = eh * s_anc[a*2+1];
        float m = -1.0f;
        #pragma unroll 5
        for (int k=0;k<KGT;k++){
            if (s_v[k]){
                float v = iou_f(px,py,pw,ph, s_gt[k][0],s_gt[k][1],s_gt[k][2],s_gt[k][3]);
                m = fmaxf(m, v);
            }
        }
        if (m > 0.7f) atomicOr(&s_hp, 1);

        int f = hw*NA + a;
        int rec = -1;
        #pragma unroll 5
        for (int k=0;k<KGT;k++)
            if (s_v[k] && s_w[k] && s_f[k]==f) rec = k;

        float conf = sigf(base[(size_t)4*HW]);
        if (rec >= 0){
            float di = 5.0f*(conf - m);           // obj_iou at winner cell == m
            float dx = sigf(base[0])          - s_d[rec][0];
            float dy = sigf(base[(size_t)HW]) - s_d[rec][1];
            float dw = ew - s_d[rec][2];
            float dh = eh - s_d[rec][3];
            float mx = -1e30f;
            for (int c=0;c<NC;c++) mx = fmaxf(mx, base[(size_t)(5+c)*HW]);
            float sm = 0.0f;
            for (int c=0;c<NC;c++) sm += expf(base[(size_t)(5+c)*HW] - mx);
            float lse = mx + logf(sm);
            float tl  = base[(size_t)(5+s_cls[rec])*HW];
            vm = 0.5*(double)(di*di)
               + 0.5*(double)(dx*dx + dy*dy + dw*dw + dh*dh)
               + (double)(lse - tl);
        } else if (s_numobj > 0){
            double c2 = 0.5*(double)(conf*conf);
            vm = c2;
            if (m >= 0.7f) vh = c2;               // subtracted later iff has_pos
        }
    }

    s_rm[tid] = vm; s_rh[tid] = vh;
    __syncthreads();
    for (int r=128; r>0; r>>=1){
        if (tid < r){ s_rm[tid]+=s_rm[tid+r]; s_rh[tid]+=s_rh[tid+r]; }
        __syncthreads();
    }
    if (tid == 0){
        g_pmain[pidx] = s_rm[0];
        g_phigh[pidx] = s_rh[0];
        g_php[pidx]   = s_hp;
    }
}

__global__ void k_final(float* __restrict__ outp, int B){
    __shared__ double s[64];
    int t = threadIdx.x;
    double v = 0.0;
    if (t < 3*B){
        double m = 0.0, h = 0.0; int hp = 0;
        int base = t*GX;
        for (int j=0;j<GX;j++){
            m += g_pmain[base+j];
            h += g_phigh[base+j];
            hp |= g_php[base+j];
        }
        v = m - (hp ? h : 0.0);
    }
    s[t] = v;
    __syncthreads();
    for (int r=32; r>0; r>>=1){
        if (t < r) s[t] += s[t+r];
        __syncthreads();
    }
    if (t == 0) outp[0] = (float)(s[0] / ((double)B * 3.0));
}

extern "C" void kernel_launch(void* const* d_in, const int* in_sizes, int n_in,
                              void* d_out, int out_size){
    const float* o0 = (const float*)d_in[0];
    const float* o1 = (const float*)d_in[1];
    const float* o2 = (const float*)d_in[2];
    const float* tgt = (const float*)d_in[3];
    const float* anc = (const float*)d_in[4];
    int B = in_sizes[3] / (KGT*5);
    int Ws[3];
    for (int i=0;i<3;i++){
        int hw = in_sizes[i] / (B*255);
        int w = 1; while (w*w < hw) w++;
        Ws[i] = w;
    }
    dim3 grid(GX, B, 3);
    k_main<<<grid, 256>>>(o0, o1, o2, tgt, anc, Ws[0], Ws[1], Ws[2], B);
    k_final<<<1, 64>>>((float*)d_out, B);
}